// round 15
// baseline (speedup 1.0000x reference)
#include <cuda_runtime.h>
#include <cuda_fp16.h>
#include <cstdint>

#define B_ 4
#define S_ 2048
#define H_ 16
#define D_ 64
#define HID 1024
#define BH_ (B_ * H_)

// ---------------------------------------------------------------------------
// Device scratch (allocation-free rule). All fp16.
// g_kh: [B,H,S,D] with d-dim PERMUTED within each 16-half group
//       (u32 w -> w<4 ? 2w : 2w-7) so mma B-fragment pairs are adjacent.
// g_vt: [B,H,D,S] with s-dim permuted the same way.
// ---------------------------------------------------------------------------
__device__ __align__(16) __half g_qh[(size_t)BH_ * S_ * D_];   // [B,H,S,D], pre-scaled, UNpermuted
__device__ __align__(16) __half g_kh[(size_t)BH_ * S_ * D_];
__device__ __align__(16) __half g_vt[(size_t)BH_ * D_ * S_];
__device__ __align__(16) __half g_ctxh[(size_t)B_ * S_ * HID]; // [B,S,HID]
__device__ __align__(16) __half g_xh[(size_t)B_ * S_ * HID];
__device__ __align__(16) __half g_wh[4 * (size_t)HID * HID];

// ---------------------------------------------------------------------------
// Helpers
// ---------------------------------------------------------------------------
__device__ __forceinline__ float ex2(float x) {
    float y;
    asm("ex2.approx.f32 %0, %1;" : "=f"(y) : "f"(x));
    return y;
}
__device__ __forceinline__ uint32_t h2u(float lo, float hi) {
    uint32_t d;
    asm("cvt.rn.f16x2.f32 %0, %1, %2;" : "=r"(d) : "f"(hi), "f"(lo));
    return d;
}
// packed fp16x2 exp2
__device__ __forceinline__ uint32_t hex2(uint32_t x) {
    uint32_t y;
    asm("ex2.approx.f16x2 %0, %1;" : "=r"(y) : "r"(x));
    return y;
}

// mma.sync m16n8k16 fp16 inputs, fp32 accumulate
__device__ __forceinline__ void mma16(float* d, const uint32_t* a, const uint32_t* b) {
    asm volatile(
        "mma.sync.aligned.m16n8k16.row.col.f32.f16.f16.f32 "
        "{%0,%1,%2,%3}, {%4,%5,%6,%7}, {%8,%9}, {%0,%1,%2,%3};"
        : "+f"(d[0]), "+f"(d[1]), "+f"(d[2]), "+f"(d[3])
        : "r"(a[0]), "r"(a[1]), "r"(a[2]), "r"(a[3]), "r"(b[0]), "r"(b[1]));
}

// ldmatrix x4 (projection kernel)
__device__ __forceinline__ void ldsm4(uint32_t* r, uint32_t a) {
    asm volatile("ldmatrix.sync.aligned.m8n8.x4.shared.b16 {%0,%1,%2,%3}, [%4];"
                 : "=r"(r[0]), "=r"(r[1]), "=r"(r[2]), "=r"(r[3]) : "r"(a));
}

__device__ __forceinline__ uint32_t smem_u32(const void* p) {
    uint32_t a;
    asm("{ .reg .u64 t; cvta.to.shared.u64 t, %1; cvt.u32.u64 %0, t; }"
        : "=r"(a) : "l"(p));
    return a;
}
__device__ __forceinline__ void cpa16(uint32_t s, const void* g) {
    asm volatile("cp.async.cg.shared.global [%0], [%1], 16;" :: "r"(s), "l"(g));
}
__device__ __forceinline__ void cpa_commit() {
    asm volatile("cp.async.commit_group;" ::: "memory");
}
template <int N> __device__ __forceinline__ void cpa_wait() {
    asm volatile("cp.async.wait_group %0;" :: "n"(N) : "memory");
}

// ---------------------------------------------------------------------------
// fp32 -> fp16 conversion, single merged kernel.
// ---------------------------------------------------------------------------
__global__ void cvt_all(const float4* __restrict__ x,
                        const float4* __restrict__ wq, const float4* __restrict__ wk,
                        const float4* __restrict__ wv, const float4* __restrict__ wo)
{
    const int XN4 = B_ * S_ * HID / 4;       // 2,097,152
    const int WN4 = HID * HID / 4;           // 262,144
    int i = blockIdx.x * blockDim.x + threadIdx.x;
    if (i < XN4) {
        float4 v = x[i];
        ((uint2*)g_xh)[i] = make_uint2(h2u(v.x, v.y), h2u(v.z, v.w));
        return;
    }
    int j = i - XN4;
    if (j >= 4 * WN4) return;
    int which = j / WN4;
    int local = j - which * WN4;
    const float4* src = (which == 0) ? wq : (which == 1) ? wk : (which == 2) ? wv : wo;
    float4 v = src[local];
    ((uint2*)g_wh)[j] = make_uint2(h2u(v.x, v.y), h2u(v.z, v.w));
}

// ---------------------------------------------------------------------------
// Projection GEMM: 128m x 128n block, 8 warps (warp 64x32), BK=32 halves.
// R15: TWO slabs per iteration over a 4-buffer ring; loads issued one full
// iteration ahead (wait_group<0> then has >=1 iteration of latency cover);
// 16 barriers instead of 32. smem 81920 B, 2 CTAs/SM.
// K/V epilogues write the fragment-pair permutation for the attention kernel.
// ---------------------------------------------------------------------------
#define PJ_A32 (128 * 20)
#define PJ_B32 (128 * 20)
static constexpr int PROJ_SMEM = 4 * (PJ_A32 + PJ_B32) * 4;  // 81920 B

__global__ __launch_bounds__(256, 2) void proj_tc(
    const __half* __restrict__ Aall, int mode,
    const float* __restrict__ bq, const float* __restrict__ bk,
    const float* __restrict__ bv, const float* __restrict__ bo,
    float* __restrict__ outflat)
{
    extern __shared__ uint32_t smu[];

    const int tid = threadIdx.x;
    const int m0  = blockIdx.y * 128;

    int which, n0g;
    const float* bias;
    if (mode == 0) {
        which = blockIdx.x >> 3;             // 0=Q 1=K 2=V (8 n-tiles each)
        n0g   = (blockIdx.x & 7) * 128;
        bias  = (which == 0) ? bq : (which == 1) ? bk : bv;
    } else {
        which = 3;
        n0g   = blockIdx.x * 128;
        bias  = bo;
    }
    const __half* Wb = g_wh + (size_t)which * HID * HID + (size_t)n0g * HID;
    const __half* Ab = Aall + (size_t)m0 * HID;

    const uint32_t sb = smem_u32(smu);

    auto load_slab = [&](int kt) {
        const int bi = kt & 3;
        const uint32_t abase = sb + (uint32_t)(bi * PJ_A32) * 4u;
        const uint32_t bbase = sb + (uint32_t)(4 * PJ_A32 + bi * PJ_B32) * 4u;
        const int k0 = kt * 32;
#pragma unroll
        for (int it = 0; it < 2; ++it) {
            int f = tid + it * 256;
            int row = f >> 2, kq = (f & 3) * 8;
            cpa16(abase + (uint32_t)(row * 20 + (f & 3) * 4) * 4u,
                  Ab + (size_t)row * HID + k0 + kq);
        }
#pragma unroll
        for (int it = 0; it < 2; ++it) {
            int f = tid + it * 256;
            int row = f >> 2, kq = (f & 3) * 8;
            cpa16(bbase + (uint32_t)(row * 20 + (f & 3) * 4) * 4u,
                  Wb + (size_t)row * HID + k0 + kq);
        }
        cpa_commit();
    };

    const int w    = tid >> 5;
    const int lane = tid & 31;
    const int r    = lane >> 2;
    const int c    = lane & 3;
    const int wm   = (w & 1) * 64;     // 2 m-groups
    const int wn   = (w >> 1) * 32;    // 4 n-groups

    const uint32_t aoff = (uint32_t)((wm + (lane & 15)) * 20 + (lane >> 4) * 4);
    const uint32_t boff = (uint32_t)((wn + ((lane >> 4) * 8) + (lane & 7)) * 20
                                     + ((lane >> 3) & 1) * 4);

    float acc[4][4][4];
#pragma unroll
    for (int i = 0; i < 4; ++i)
#pragma unroll
        for (int j = 0; j < 4; ++j)
#pragma unroll
            for (int q = 0; q < 4; ++q) acc[i][j][q] = 0.f;

    load_slab(0);
    load_slab(1);

    for (int kt2 = 0; kt2 < 32; kt2 += 2) {
        cpa_wait<0>();          // slabs kt2, kt2+1 resident (issued 1 iter ago)
        __syncthreads();        // all warps done with buffers (kt2+2)&3,(kt2+3)&3
        if (kt2 + 2 < 32) {     // prefetch next pair into the freed buffers
            load_slab(kt2 + 2);
            load_slab(kt2 + 3);
        }

#pragma unroll
        for (int u = 0; u < 2; ++u) {
            const int bi = (kt2 + u) & 3;
            const uint32_t abuf = sb + (uint32_t)(bi * PJ_A32) * 4u;
            const uint32_t bbuf = sb + (uint32_t)(4 * PJ_A32 + bi * PJ_B32) * 4u;

#pragma unroll
            for (int ks = 0; ks < 2; ++ks) {
                uint32_t af[4][4];
#pragma unroll
                for (int i = 0; i < 4; ++i)
                    ldsm4(af[i], abuf + (aoff + (uint32_t)(i * 320 + ks * 8)) * 4u);
                uint32_t bg[2][4];
#pragma unroll
                for (int g = 0; g < 2; ++g)
                    ldsm4(bg[g], bbuf + (boff + (uint32_t)(g * 320 + ks * 8)) * 4u);
#pragma unroll
                for (int g = 0; g < 2; ++g)
#pragma unroll
                    for (int i = 0; i < 4; ++i) {
                        mma16(acc[i][2 * g],     af[i], &bg[g][0]);
                        mma16(acc[i][2 * g + 1], af[i], &bg[g][2]);
                    }
            }
        }
    }

    // Epilogue
    if (mode == 0) {
        const float SCQ = 0.125f * 1.4426950408889634f;
#pragma unroll
        for (int j = 0; j < 4; ++j) {
            const int nl = n0g + wn + j * 8 + 2 * c;
            const float b0 = bias[nl], b1 = bias[nl + 1];
            const int h  = nl >> 6;
            const int dd = nl & 63;                 // even
            // fragment-pair permutation of u32 index u within 8-u32 groups
            const int u  = dd >> 1;
            const int pw = u & 7;
            const int ndd = ((u & ~7) | ((pw < 4) ? 2 * pw : 2 * pw - 7)) * 2;
#pragma unroll
            for (int i = 0; i < 4; ++i) {
                int m = m0 + wm + i * 16 + r;
                int bi = m >> 11, s = m & 2047;     // s & 15 == r < 8
                float v0 = acc[i][j][0] + b0, v1 = acc[i][j][1] + b1;
                float v2 = acc[i][j][2] + b0, v3 = acc[i][j][3] + b1;
                if (which == 0) {
                    __half* p = g_qh + (((size_t)(bi * H_ + h) * S_ + s) * D_ + dd);
                    *(uint32_t*)p = h2u(v0 * SCQ, v1 * SCQ);
                    *(uint32_t*)(p + 8 * D_) = h2u(v2 * SCQ, v3 * SCQ);
                } else if (which == 1) {
                    __half* p = g_kh + (((size_t)(bi * H_ + h) * S_ + s) * D_ + ndd);
                    *(uint32_t*)p = h2u(v0, v1);
                    *(uint32_t*)(p + 8 * D_) = h2u(v2, v3);
                } else {
                    // V transposed [B,H,D,S], s-dim permuted.
                    const int sw = (s >> 1) & 7;    // < 4 since s&15 = r < 8
                    const int ns = (s & ~15) | (4 * sw + (s & 1));
                    __half* p = g_vt + (((size_t)(bi * H_ + h) * D_ + dd) * S_ + ns);
                    p[0]      = __float2half_rn(v0);   // (dd,   s)
                    p[S_]     = __float2half_rn(v1);   // (dd+1, s)
                    p[2]      = __float2half_rn(v2);   // (dd,   s+8) -> ns+2
                    p[S_ + 2] = __float2half_rn(v3);   // (dd+1, s+8)
                }
            }
        }
    } else {
#pragma unroll
        for (int j = 0; j < 4; ++j) {
            const int n = n0g + wn + j * 8 + 2 * c;
            const float b0 = bias[n], b1 = bias[n + 1];
#pragma unroll
            for (int i = 0; i < 4; ++i) {
                int m = m0 + wm + i * 16 + r;
                float* p = outflat + (size_t)m * HID + n;
                *(float2*)p = make_float2(acc[i][j][0] + b0, acc[i][j][1] + b1);
                *(float2*)(p + 8 * HID) =
                    make_float2(acc[i][j][2] + b0, acc[i][j][3] + b1);
            }
        }
    }
}

// ---------------------------------------------------------------------------
// Flash attention, R15: FROZEN-MAX softmax. Row max computed once on tile 0
// (scores are tightly concentrated; later tiles exceed it by <~1 in log2 ->
// p <= 2, far from fp16 overflow). No per-tile max reduce, no rescale, no f.
// Everything else frozen from R13 (packed fp16x2 exp2, LDS.64 B-frags via
// permuted K/V layouts, ones-column MMA row-sum, 3-stage cp.async pipeline).
// ---------------------------------------------------------------------------
#define AT_ST 40
#define AT_TILE (64 * AT_ST)          // u32 per K or V stage
static constexpr int ATTN_SMEM = 6 * AT_TILE * 4;   // 61440 B

__global__ __launch_bounds__(256, 2) void attn_tc(const float* __restrict__ head_mask)
{
    extern __shared__ uint32_t smu[];

    const int tid = threadIdx.x;
    const int bh  = blockIdx.y;
    const int s0  = blockIdx.x * 128;

    const __half* K = g_kh + (size_t)bh * S_ * D_;
    const __half* V = g_vt + (size_t)bh * D_ * S_;

    const int w    = tid >> 5;
    const int lane = tid & 31;
    const int r    = lane >> 2;
    const int c    = lane & 3;
    const int wm   = w * 16;

    const uint32_t sb = smem_u32(smu);

    // Q fragments from gmem (fp16, pre-scaled, unpermuted).
    uint32_t qf[4][4];
    {
        const uint32_t* Qp = (const uint32_t*)(g_qh + (size_t)bh * S_ * D_);
        const uint32_t* q0 = Qp + (size_t)(s0 + wm + r) * 32;
        const uint32_t* q1 = q0 + 8 * 32;
#pragma unroll
        for (int ks = 0; ks < 4; ++ks) {
            qf[ks][0] = q0[ks * 8 + c];
            qf[ks][1] = q1[ks * 8 + c];
            qf[ks][2] = q0[ks * 8 + c + 4];
            qf[ks][3] = q1[ks * 8 + c + 4];
        }
    }

    auto load_tile = [&](int kt) {
        const int bi = kt % 3;
        const uint32_t kd = sb + (uint32_t)(bi * AT_TILE) * 4u;        // K stage bi
        const uint32_t vd = sb + (uint32_t)((3 + bi) * AT_TILE) * 4u;  // V stage bi
#pragma unroll
        for (int it = 0; it < 2; ++it) {
            int f = tid + it * 256;          // 0..511
            int row = f >> 3;
            int dq  = (f & 7) * 8;           // halves (verbatim row copy)
            cpa16(kd + (uint32_t)(row * AT_ST + (f & 7) * 4) * 4u,
                  K + (size_t)(kt * 64 + row) * D_ + dq);
            cpa16(vd + (uint32_t)(row * AT_ST + (f & 7) * 4) * 4u,
                  V + (size_t)row * S_ + kt * 64 + dq);
        }
        cpa_commit();
    };

    float m0 = 0.f, m1 = 0.f;       // frozen after tile 0
    float oacc[8][4];
#pragma unroll
    for (int j = 0; j < 8; ++j)
#pragma unroll
        for (int q = 0; q < 4; ++q) oacc[j][q] = 0.f;
    float lacc[4] = {0.f, 0.f, 0.f, 0.f};   // ones-column MMA accumulator

    load_tile(0);
    load_tile(1);

    const uint32_t onesb[2] = {0x3C003C00u, 0x3C003C00u};   // fp16 1.0 x4

    for (int kt = 0; kt < S_ / 64; ++kt) {
        cpa_wait<1>();
        __syncthreads();
        if (kt + 2 < S_ / 64) load_tile(kt + 2);
        else cpa_commit();

        // canonical stage selects (single addend from smu)
        const uint32_t* ks_ = smu + (size_t)(kt % 3) * AT_TILE;
        const uint32_t* vs_ = smu + (size_t)(3 + (kt % 3)) * AT_TILE;

        // --- S = Q @ K^T (log2e space); B-frags are single LDS.64 ---
        float sacc[8][4];
#pragma unroll
        for (int j = 0; j < 8; ++j)
#pragma unroll
            for (int q = 0; q < 4; ++q) sacc[j][q] = 0.f;

#pragma unroll
        for (int ksb = 0; ksb < 4; ++ksb) {
#pragma unroll
            for (int j = 0; j < 8; ++j) {
                uint2 b2 = *(const uint2*)(ks_ + (8 * j + r) * AT_ST + 8 * ksb + 2 * c);
                uint32_t bf[2] = { b2.x, b2.y };
                mma16(sacc[j], qf[ksb], bf);
            }
        }

        // --- frozen max: reduce once, on the first tile only ---
        if (kt == 0) {
            float mx0 = sacc[0][0], mx1 = sacc[0][2];
#pragma unroll
            for (int j = 0; j < 8; ++j) {
                mx0 = fmaxf(mx0, fmaxf(sacc[j][0], sacc[j][1]));
                mx1 = fmaxf(mx1, fmaxf(sacc[j][2], sacc[j][3]));
            }
            mx0 = fmaxf(mx0, __shfl_xor_sync(0xffffffffu, mx0, 1));
            mx0 = fmaxf(mx0, __shfl_xor_sync(0xffffffffu, mx0, 2));
            mx1 = fmaxf(mx1, __shfl_xor_sync(0xffffffffu, mx1, 1));
            mx1 = fmaxf(mx1, __shfl_xor_sync(0xffffffffu, mx1, 2));
            m0 = mx0;
            m1 = mx1;
        }

        // exp via packed fp16x2 ex2 (args near 0 for dominant entries)
        uint32_t pf[4][4];
#pragma unroll
        for (int t = 0; t < 4; ++t) {
            pf[t][0] = hex2(h2u(sacc[2 * t][0] - m0,     sacc[2 * t][1] - m0));
            pf[t][1] = hex2(h2u(sacc[2 * t][2] - m1,     sacc[2 * t][3] - m1));
            pf[t][2] = hex2(h2u(sacc[2 * t + 1][0] - m0, sacc[2 * t + 1][1] - m0));
            pf[t][3] = hex2(h2u(sacc[2 * t + 1][2] - m1, sacc[2 * t + 1][3] - m1));
        }

        // --- O += P@V and l += P@1 (no rescale: max is frozen) ---
#pragma unroll
        for (int t = 0; t < 4; ++t) {
            mma16(lacc, pf[t], onesb);
#pragma unroll
            for (int j = 0; j < 8; ++j) {
                uint2 b2 = *(const uint2*)(vs_ + (8 * j + r) * AT_ST + 8 * t + 2 * c);
                uint32_t bf[2] = { b2.x, b2.y };
                mma16(oacc[j], pf[t], bf);
            }
        }
    }

    // Epilogue: normalize, head-mask, write ctx fp16 [B,S,HID]
    const int bix = bh >> 4;
    const int h   = bh & 15;
    const float mask = head_mask[h];
    const float inv0 = mask / lacc[0];
    const float inv1 = mask / lacc[2];
    const int s = s0 + wm + r;
#pragma unroll
    for (int j = 0; j < 8; ++j) {
        int dd = 8 * j + 2 * c;
        __half* p = g_ctxh + ((size_t)bix * S_ + s) * HID + h * 64 + dd;
        *(uint32_t*)p = h2u(oacc[j][0] * inv0, oacc[j][1] * inv0);
        *(uint32_t*)(p + 8 * HID) = h2u(oacc[j][2] * inv1, oacc[j][3] * inv1);
    }
}

// ---------------------------------------------------------------------------
extern "C" void kernel_launch(void* const* d_in, const int* in_sizes, int n_in,
                              void* d_out, int out_size)
{
    const float* x  = (const float*)d_in[0];
    const float* Wq = (const float*)d_in[1];
    const float* bq = (const float*)d_in[2];
    const float* Wk = (const float*)d_in[3];
    const float* bk = (const float*)d_in[4];
    const float* Wv = (const float*)d_in[5];
    const float* bv = (const float*)d_in[6];
    const float* Wo = (const float*)d_in[7];
    const float* bo = (const float*)d_in[8];
    const float* head_mask = (const float*)d_in[9];
    float* out = (float*)d_out;

    static bool attr_set = false;
    if (!attr_set) {
        cudaFuncSetAttribute(proj_tc, cudaFuncAttributeMaxDynamicSharedMemorySize, PROJ_SMEM);
        cudaFuncSetAttribute(attn_tc, cudaFuncAttributeMaxDynamicSharedMemorySize, ATTN_SMEM);
        attr_set = true;
    }

    // fp32 -> fp16 conversion (x + all four weight matrices, one launch)
    const int total4 = B_ * S_ * HID / 4 + 4 * (HID * HID / 4);   // 3,145,728
    cvt_all<<<(total4 + 255) / 256, 256>>>((const float4*)x,
                                           (const float4*)Wq, (const float4*)Wk,
                                           (const float4*)Wv, (const float4*)Wo);

    __half* xh_dev;  cudaGetSymbolAddress((void**)&xh_dev,  g_xh);
    __half* ctx_dev; cudaGetSymbolAddress((void**)&ctx_dev, g_ctxh);

    // QKV projection: 24 x 64 blocks of 128m x 128n (8 n-tiles per matrix)
    proj_tc<<<dim3(24, 64), 256, PROJ_SMEM>>>(xh_dev, 0, bq, bk, bv, bo, nullptr);

    // Attention: 16 q-tiles x 64 bh
    attn_tc<<<dim3(16, 64), 256, ATTN_SMEM>>>(head_mask);

    // O projection: 8 x 64 blocks of 128m x 128n
    proj_tc<<<dim3(8, 64), 256, PROJ_SMEM>>>(ctx_dev, 1, bq, bk, bv, bo, out);
}

// round 16
// speedup vs baseline: 1.5632x; 1.5632x over previous
#include <cuda_runtime.h>
#include <cuda_fp16.h>
#include <cstdint>

#define B_ 4
#define S_ 2048
#define H_ 16
#define D_ 64
#define HID 1024
#define BH_ (B_ * H_)

// ---------------------------------------------------------------------------
// Device scratch (allocation-free rule). All fp16.
// g_kh: [B,H,S,D] with d-dim PERMUTED within each 16-half group
//       (u32 w -> w<4 ? 2w : 2w-7) so mma B-fragment pairs are adjacent.
// g_vt: [B,H,D,S] with s-dim permuted the same way.
// ---------------------------------------------------------------------------
__device__ __align__(16) __half g_qh[(size_t)BH_ * S_ * D_];   // [B,H,S,D], pre-scaled, UNpermuted
__device__ __align__(16) __half g_kh[(size_t)BH_ * S_ * D_];
__device__ __align__(16) __half g_vt[(size_t)BH_ * D_ * S_];
__device__ __align__(16) __half g_ctxh[(size_t)B_ * S_ * HID]; // [B,S,HID]
__device__ __align__(16) __half g_xh[(size_t)B_ * S_ * HID];
__device__ __align__(16) __half g_wh[4 * (size_t)HID * HID];

// ---------------------------------------------------------------------------
// Helpers
// ---------------------------------------------------------------------------
__device__ __forceinline__ float ex2(float x) {
    float y;
    asm("ex2.approx.f32 %0, %1;" : "=f"(y) : "f"(x));
    return y;
}
__device__ __forceinline__ uint32_t h2u(float lo, float hi) {
    uint32_t d;
    asm("cvt.rn.f16x2.f32 %0, %1, %2;" : "=r"(d) : "f"(hi), "f"(lo));
    return d;
}
// packed fp16x2 exp2 — halves MUFU pressure in the softmax
__device__ __forceinline__ uint32_t hex2(uint32_t x) {
    uint32_t y;
    asm("ex2.approx.f16x2 %0, %1;" : "=r"(y) : "r"(x));
    return y;
}

// mma.sync m16n8k16 fp16 inputs, fp32 accumulate
__device__ __forceinline__ void mma16(float* d, const uint32_t* a, const uint32_t* b) {
    asm volatile(
        "mma.sync.aligned.m16n8k16.row.col.f32.f16.f16.f32 "
        "{%0,%1,%2,%3}, {%4,%5,%6,%7}, {%8,%9}, {%0,%1,%2,%3};"
        : "+f"(d[0]), "+f"(d[1]), "+f"(d[2]), "+f"(d[3])
        : "r"(a[0]), "r"(a[1]), "r"(a[2]), "r"(a[3]), "r"(b[0]), "r"(b[1]));
}

// ldmatrix x4 (projection kernel)
__device__ __forceinline__ void ldsm4(uint32_t* r, uint32_t a) {
    asm volatile("ldmatrix.sync.aligned.m8n8.x4.shared.b16 {%0,%1,%2,%3}, [%4];"
                 : "=r"(r[0]), "=r"(r[1]), "=r"(r[2]), "=r"(r[3]) : "r"(a));
}

__device__ __forceinline__ uint32_t smem_u32(const void* p) {
    uint32_t a;
    asm("{ .reg .u64 t; cvta.to.shared.u64 t, %1; cvt.u32.u64 %0, t; }"
        : "=r"(a) : "l"(p));
    return a;
}
__device__ __forceinline__ void cpa16(uint32_t s, const void* g) {
    asm volatile("cp.async.cg.shared.global [%0], [%1], 16;" :: "r"(s), "l"(g));
}
__device__ __forceinline__ void cpa_commit() {
    asm volatile("cp.async.commit_group;" ::: "memory");
}
template <int N> __device__ __forceinline__ void cpa_wait() {
    asm volatile("cp.async.wait_group %0;" :: "n"(N) : "memory");
}

// ---------------------------------------------------------------------------
// fp32 -> fp16 conversion, single merged kernel.
// ---------------------------------------------------------------------------
__global__ void cvt_all(const float4* __restrict__ x,
                        const float4* __restrict__ wq, const float4* __restrict__ wk,
                        const float4* __restrict__ wv, const float4* __restrict__ wo)
{
    const int XN4 = B_ * S_ * HID / 4;       // 2,097,152
    const int WN4 = HID * HID / 4;           // 262,144
    int i = blockIdx.x * blockDim.x + threadIdx.x;
    if (i < XN4) {
        float4 v = x[i];
        ((uint2*)g_xh)[i] = make_uint2(h2u(v.x, v.y), h2u(v.z, v.w));
        return;
    }
    int j = i - XN4;
    if (j >= 4 * WN4) return;
    int which = j / WN4;
    int local = j - which * WN4;
    const float4* src = (which == 0) ? wq : (which == 1) ? wk : (which == 2) ? wv : wo;
    float4 v = src[local];
    ((uint2*)g_wh)[j] = make_uint2(h2u(v.x, v.y), h2u(v.z, v.w));
}

// ---------------------------------------------------------------------------
// Projection GEMM R16: 128m x 128n block, 8 warps (warp 64x32), BK=64 halves.
// Same 3-stage / wait_group<1> / one-barrier-per-slab control flow as R13
// (proven), but slabs are 2x deeper: 16 barriers total, 64 MMAs/warp between
// barriers. Stage = 36864 B, 3 stages = 110592 B, 2 CTAs/SM (221 KB < 227 KB).
// Row stride 36 u32 (4l mod 32 covers all banks for ldmatrix phases).
// K/V epilogues write the fragment-pair permutation for the attention kernel.
// ---------------------------------------------------------------------------
#define PJ_A32 (128 * 36)
#define PJ_B32 (128 * 36)
static constexpr int PROJ_SMEM = 3 * (PJ_A32 + PJ_B32) * 4;  // 110592 B

__global__ __launch_bounds__(256, 2) void proj_tc(
    const __half* __restrict__ Aall, int mode,
    const float* __restrict__ bq, const float* __restrict__ bk,
    const float* __restrict__ bv, const float* __restrict__ bo,
    float* __restrict__ outflat)
{
    extern __shared__ uint32_t smu[];

    const int tid = threadIdx.x;
    const int m0  = blockIdx.y * 128;

    int which, n0g;
    const float* bias;
    if (mode == 0) {
        which = blockIdx.x >> 3;             // 0=Q 1=K 2=V (8 n-tiles each)
        n0g   = (blockIdx.x & 7) * 128;
        bias  = (which == 0) ? bq : (which == 1) ? bk : bv;
    } else {
        which = 3;
        n0g   = blockIdx.x * 128;
        bias  = bo;
    }
    const __half* Wb = g_wh + (size_t)which * HID * HID + (size_t)n0g * HID;
    const __half* Ab = Aall + (size_t)m0 * HID;

    const uint32_t sb = smem_u32(smu);

    // BK=64 slab: A and B are 128 rows x 64 halves each (8 x 16B per row)
    auto load_slab = [&](int kt) {
        const int bi = kt % 3;
        const uint32_t abase = sb + (uint32_t)(bi * PJ_A32) * 4u;
        const uint32_t bbase = sb + (uint32_t)(3 * PJ_A32 + bi * PJ_B32) * 4u;
        const int k0 = kt * 64;
#pragma unroll
        for (int it = 0; it < 4; ++it) {
            int f = tid + it * 256;              // 0..1023
            int row = f >> 3, kq = (f & 7) * 8;  // halves
            cpa16(abase + (uint32_t)(row * 36 + (f & 7) * 4) * 4u,
                  Ab + (size_t)row * HID + k0 + kq);
        }
#pragma unroll
        for (int it = 0; it < 4; ++it) {
            int f = tid + it * 256;
            int row = f >> 3, kq = (f & 7) * 8;
            cpa16(bbase + (uint32_t)(row * 36 + (f & 7) * 4) * 4u,
                  Wb + (size_t)row * HID + k0 + kq);
        }
        cpa_commit();
    };

    const int w    = tid >> 5;
    const int lane = tid & 31;
    const int r    = lane >> 2;
    const int c    = lane & 3;
    const int wm   = (w & 1) * 64;     // 2 m-groups
    const int wn   = (w >> 1) * 32;    // 4 n-groups

    const uint32_t aoff = (uint32_t)((wm + (lane & 15)) * 36 + (lane >> 4) * 4);
    const uint32_t boff = (uint32_t)((wn + ((lane >> 4) * 8) + (lane & 7)) * 36
                                     + ((lane >> 3) & 1) * 4);

    float acc[4][4][4];
#pragma unroll
    for (int i = 0; i < 4; ++i)
#pragma unroll
        for (int j = 0; j < 4; ++j)
#pragma unroll
            for (int q = 0; q < 4; ++q) acc[i][j][q] = 0.f;

    load_slab(0);
    load_slab(1);

    for (int kt = 0; kt < 16; ++kt) {
        cpa_wait<1>();          // slab kt resident; kt+1 may still be in flight
        __syncthreads();        // all warps done with buffer (kt+2)%3
        if (kt + 2 < 16) load_slab(kt + 2);
        else cpa_commit();      // keep group accounting uniform

        const uint32_t abuf = sb + (uint32_t)((kt % 3) * PJ_A32) * 4u;
        const uint32_t bbuf = sb + (uint32_t)(3 * PJ_A32 + (kt % 3) * PJ_B32) * 4u;

#pragma unroll
        for (int ks = 0; ks < 4; ++ks) {          // 4 k16 chunks per BK=64
            uint32_t af[4][4];
#pragma unroll
            for (int i = 0; i < 4; ++i)
                ldsm4(af[i], abuf + (aoff + (uint32_t)(i * 576 + ks * 8)) * 4u);
            uint32_t bg[2][4];
#pragma unroll
            for (int g = 0; g < 2; ++g)
                ldsm4(bg[g], bbuf + (boff + (uint32_t)(g * 576 + ks * 8)) * 4u);
#pragma unroll
            for (int g = 0; g < 2; ++g)
#pragma unroll
                for (int i = 0; i < 4; ++i) {
                    mma16(acc[i][2 * g],     af[i], &bg[g][0]);
                    mma16(acc[i][2 * g + 1], af[i], &bg[g][2]);
                }
        }
    }

    // Epilogue
    if (mode == 0) {
        const float SCQ = 0.125f * 1.4426950408889634f;
#pragma unroll
        for (int j = 0; j < 4; ++j) {
            const int nl = n0g + wn + j * 8 + 2 * c;
            const float b0 = bias[nl], b1 = bias[nl + 1];
            const int h  = nl >> 6;
            const int dd = nl & 63;                 // even
            // fragment-pair permutation of u32 index u within 8-u32 groups
            const int u  = dd >> 1;
            const int pw = u & 7;
            const int ndd = ((u & ~7) | ((pw < 4) ? 2 * pw : 2 * pw - 7)) * 2;
#pragma unroll
            for (int i = 0; i < 4; ++i) {
                int m = m0 + wm + i * 16 + r;
                int bi = m >> 11, s = m & 2047;     // s & 15 == r < 8
                float v0 = acc[i][j][0] + b0, v1 = acc[i][j][1] + b1;
                float v2 = acc[i][j][2] + b0, v3 = acc[i][j][3] + b1;
                if (which == 0) {
                    __half* p = g_qh + (((size_t)(bi * H_ + h) * S_ + s) * D_ + dd);
                    *(uint32_t*)p = h2u(v0 * SCQ, v1 * SCQ);
                    *(uint32_t*)(p + 8 * D_) = h2u(v2 * SCQ, v3 * SCQ);
                } else if (which == 1) {
                    __half* p = g_kh + (((size_t)(bi * H_ + h) * S_ + s) * D_ + ndd);
                    *(uint32_t*)p = h2u(v0, v1);
                    *(uint32_t*)(p + 8 * D_) = h2u(v2, v3);
                } else {
                    // V transposed [B,H,D,S], s-dim permuted.
                    const int sw = (s >> 1) & 7;    // < 4 since s&15 = r < 8
                    const int ns = (s & ~15) | (4 * sw + (s & 1));
                    __half* p = g_vt + (((size_t)(bi * H_ + h) * D_ + dd) * S_ + ns);
                    p[0]      = __float2half_rn(v0);   // (dd,   s)
                    p[S_]     = __float2half_rn(v1);   // (dd+1, s)
                    p[2]      = __float2half_rn(v2);   // (dd,   s+8) -> ns+2
                    p[S_ + 2] = __float2half_rn(v3);   // (dd+1, s+8)
                }
            }
        }
    } else {
#pragma unroll
        for (int j = 0; j < 4; ++j) {
            const int n = n0g + wn + j * 8 + 2 * c;
            const float b0 = bias[n], b1 = bias[n + 1];
#pragma unroll
            for (int i = 0; i < 4; ++i) {
                int m = m0 + wm + i * 16 + r;
                float* p = outflat + (size_t)m * HID + n;
                *(float2*)p = make_float2(acc[i][j][0] + b0, acc[i][j][1] + b1);
                *(float2*)(p + 8 * HID) =
                    make_float2(acc[i][j][2] + b0, acc[i][j][3] + b1);
            }
        }
    }
}

// ---------------------------------------------------------------------------
// Flash attention (R13 frozen: running max + rescale, packed fp16x2 exp2,
// LDS.64 B-frags via permuted K/V layouts, ones-column MMA row-sum,
// 3-stage cp.async pipeline, stride 40).  Measured 206 us @ tensor 58%.
// ---------------------------------------------------------------------------
#define AT_ST 40
#define AT_TILE (64 * AT_ST)          // u32 per K or V stage
static constexpr int ATTN_SMEM = 6 * AT_TILE * 4;   // 61440 B

__global__ __launch_bounds__(256, 2) void attn_tc(const float* __restrict__ head_mask)
{
    extern __shared__ uint32_t smu[];

    const int tid = threadIdx.x;
    const int bh  = blockIdx.y;
    const int s0  = blockIdx.x * 128;

    const __half* K = g_kh + (size_t)bh * S_ * D_;
    const __half* V = g_vt + (size_t)bh * D_ * S_;

    const int w    = tid >> 5;
    const int lane = tid & 31;
    const int r    = lane >> 2;
    const int c    = lane & 3;
    const int wm   = w * 16;

    const uint32_t sb = smem_u32(smu);

    // Q fragments from gmem (fp16, pre-scaled, unpermuted).
    uint32_t qf[4][4];
    {
        const uint32_t* Qp = (const uint32_t*)(g_qh + (size_t)bh * S_ * D_);
        const uint32_t* q0 = Qp + (size_t)(s0 + wm + r) * 32;
        const uint32_t* q1 = q0 + 8 * 32;
#pragma unroll
        for (int ks = 0; ks < 4; ++ks) {
            qf[ks][0] = q0[ks * 8 + c];
            qf[ks][1] = q1[ks * 8 + c];
            qf[ks][2] = q0[ks * 8 + c + 4];
            qf[ks][3] = q1[ks * 8 + c + 4];
        }
    }

    auto load_tile = [&](int kt) {
        const int bi = kt % 3;
        const uint32_t kd = sb + (uint32_t)(bi * AT_TILE) * 4u;        // K stage bi
        const uint32_t vd = sb + (uint32_t)((3 + bi) * AT_TILE) * 4u;  // V stage bi
#pragma unroll
        for (int it = 0; it < 2; ++it) {
            int f = tid + it * 256;          // 0..511
            int row = f >> 3;
            int dq  = (f & 7) * 8;           // halves (verbatim row copy)
            cpa16(kd + (uint32_t)(row * AT_ST + (f & 7) * 4) * 4u,
                  K + (size_t)(kt * 64 + row) * D_ + dq);
            cpa16(vd + (uint32_t)(row * AT_ST + (f & 7) * 4) * 4u,
                  V + (size_t)row * S_ + kt * 64 + dq);
        }
        cpa_commit();
    };

    float m0 = -1e30f, m1 = -1e30f;
    float oacc[8][4];
#pragma unroll
    for (int j = 0; j < 8; ++j)
#pragma unroll
        for (int q = 0; q < 4; ++q) oacc[j][q] = 0.f;
    float lacc[4] = {0.f, 0.f, 0.f, 0.f};   // ones-column MMA accumulator

    load_tile(0);
    load_tile(1);

    const uint32_t onesb[2] = {0x3C003C00u, 0x3C003C00u};   // fp16 1.0 x4

    for (int kt = 0; kt < S_ / 64; ++kt) {
        cpa_wait<1>();
        __syncthreads();
        if (kt + 2 < S_ / 64) load_tile(kt + 2);
        else cpa_commit();

        // canonical stage selects (single addend from smu)
        const uint32_t* ks_ = smu + (size_t)(kt % 3) * AT_TILE;
        const uint32_t* vs_ = smu + (size_t)(3 + (kt % 3)) * AT_TILE;

        // --- S = Q @ K^T (log2e space); B-frags are single LDS.64 ---
        float sacc[8][4];
#pragma unroll
        for (int j = 0; j < 8; ++j)
#pragma unroll
            for (int q = 0; q < 4; ++q) sacc[j][q] = 0.f;

#pragma unroll
        for (int ksb = 0; ksb < 4; ++ksb) {
#pragma unroll
            for (int j = 0; j < 8; ++j) {
                uint2 b2 = *(const uint2*)(ks_ + (8 * j + r) * AT_ST + 8 * ksb + 2 * c);
                uint32_t bf[2] = { b2.x, b2.y };
                mma16(sacc[j], qf[ksb], bf);
            }
        }

        // --- register softmax max (rows r, r+8) ---
        float mx0 = sacc[0][0], mx1 = sacc[0][2];
#pragma unroll
        for (int j = 0; j < 8; ++j) {
            mx0 = fmaxf(mx0, fmaxf(sacc[j][0], sacc[j][1]));
            mx1 = fmaxf(mx1, fmaxf(sacc[j][2], sacc[j][3]));
        }
        mx0 = fmaxf(mx0, __shfl_xor_sync(0xffffffffu, mx0, 1));
        mx0 = fmaxf(mx0, __shfl_xor_sync(0xffffffffu, mx0, 2));
        mx1 = fmaxf(mx1, __shfl_xor_sync(0xffffffffu, mx1, 1));
        mx1 = fmaxf(mx1, __shfl_xor_sync(0xffffffffu, mx1, 2));

        const float nm0 = fmaxf(m0, mx0);
        const float nm1 = fmaxf(m1, mx1);
        const float f0 = ex2(m0 - nm0);
        const float f1 = ex2(m1 - nm1);
        m0 = nm0; m1 = nm1;

        // exp via packed fp16x2 ex2: pack (s - m) pairs, one MUFU per pair.
        uint32_t pf[4][4];
#pragma unroll
        for (int t = 0; t < 4; ++t) {
            pf[t][0] = hex2(h2u(sacc[2 * t][0] - nm0,     sacc[2 * t][1] - nm0));
            pf[t][1] = hex2(h2u(sacc[2 * t][2] - nm1,     sacc[2 * t][3] - nm1));
            pf[t][2] = hex2(h2u(sacc[2 * t + 1][0] - nm0, sacc[2 * t + 1][1] - nm0));
            pf[t][3] = hex2(h2u(sacc[2 * t + 1][2] - nm1, sacc[2 * t + 1][3] - nm1));
        }

        // --- rescale accumulators (unconditional — overlaps with MMAs) ---
#pragma unroll
        for (int j = 0; j < 8; ++j) {
            oacc[j][0] *= f0; oacc[j][1] *= f0;
            oacc[j][2] *= f1; oacc[j][3] *= f1;
        }
        lacc[0] *= f0; lacc[2] *= f1;

        // --- O += P@V and l += P@1 ---
#pragma unroll
        for (int t = 0; t < 4; ++t) {
            mma16(lacc, pf[t], onesb);
#pragma unroll
            for (int j = 0; j < 8; ++j) {
                uint2 b2 = *(const uint2*)(vs_ + (8 * j + r) * AT_ST + 8 * t + 2 * c);
                uint32_t bf[2] = { b2.x, b2.y };
                mma16(oacc[j], pf[t], bf);
            }
        }
    }

    // Epilogue: normalize, head-mask, write ctx fp16 [B,S,HID]
    const int bix = bh >> 4;
    const int h   = bh & 15;
    const float mask = head_mask[h];
    const float inv0 = mask / lacc[0];
    const float inv1 = mask / lacc[2];
    const int s = s0 + wm + r;
#pragma unroll
    for (int j = 0; j < 8; ++j) {
        int dd = 8 * j + 2 * c;
        __half* p = g_ctxh + ((size_t)bix * S_ + s) * HID + h * 64 + dd;
        *(uint32_t*)p = h2u(oacc[j][0] * inv0, oacc[j][1] * inv0);
        *(uint32_t*)(p + 8 * HID) = h2u(oacc[j][2] * inv1, oacc[j][3] * inv1);
    }
}

// ---------------------------------------------------------------------------
extern "C" void kernel_launch(void* const* d_in, const int* in_sizes, int n_in,
                              void* d_out, int out_size)
{
    const float* x  = (const float*)d_in[0];
    const float* Wq = (const float*)d_in[1];
    const float* bq = (const float*)d_in[2];
    const float* Wk = (const float*)d_in[3];
    const float* bk = (const float*)d_in[4];
    const float* Wv = (const float*)d_in[5];
    const float* bv = (const float*)d_in[6];
    const float* Wo = (const float*)d_in[7];
    const float* bo = (const float*)d_in[8];
    const float* head_mask = (const float*)d_in[9];
    float* out = (float*)d_out;

    static bool attr_set = false;
    if (!attr_set) {
        cudaFuncSetAttribute(proj_tc, cudaFuncAttributeMaxDynamicSharedMemorySize, PROJ_SMEM);
        cudaFuncSetAttribute(attn_tc, cudaFuncAttributeMaxDynamicSharedMemorySize, ATTN_SMEM);
        attr_set = true;
    }

    // fp32 -> fp16 conversion (x + all four weight matrices, one launch)
    const int total4 = B_ * S_ * HID / 4 + 4 * (HID * HID / 4);   // 3,145,728
    cvt_all<<<(total4 + 255) / 256, 256>>>((const float4*)x,
                                           (const float4*)Wq, (const float4*)Wk,
                                           (const float4*)Wv, (const float4*)Wo);

    __half* xh_dev;  cudaGetSymbolAddress((void**)&xh_dev,  g_xh);
    __half* ctx_dev; cudaGetSymbolAddress((void**)&ctx_dev, g_ctxh);

    // QKV projection: 24 x 64 blocks of 128m x 128n (8 n-tiles per matrix)
    proj_tc<<<dim3(24, 64), 256, PROJ_SMEM>>>(xh_dev, 0, bq, bk, bv, bo, nullptr);

    // Attention: 16 q-tiles x 64 bh
    attn_tc<<<dim3(16, 64), 256, ATTN_SMEM>>>(head_mask);

    // O projection: 8 x 64 blocks of 128m x 128n
    proj_tc<<<dim3(8, 64), 256, PROJ_SMEM>>>(ctx_dev, 1, bq, bk, bv, bo, out);
}

// round 17
// speedup vs baseline: 1.5830x; 1.0127x over previous
#include <cuda_runtime.h>
#include <cuda_fp16.h>
#include <cstdint>

#define B_ 4
#define S_ 2048
#define H_ 16
#define D_ 64
#define HID 1024
#define BH_ (B_ * H_)

// ---------------------------------------------------------------------------
// Device scratch (allocation-free rule). All fp16.
// g_kh: [B,H,S,D] with d-dim PERMUTED within each 16-half group
//       (u32 w -> w<4 ? 2w : 2w-7) so mma B-fragment pairs are adjacent.
// g_vt: [B,H,D,S] with s-dim permuted the same way.
// ---------------------------------------------------------------------------
__device__ __align__(16) __half g_qh[(size_t)BH_ * S_ * D_];   // [B,H,S,D], pre-scaled, UNpermuted
__device__ __align__(16) __half g_kh[(size_t)BH_ * S_ * D_];
__device__ __align__(16) __half g_vt[(size_t)BH_ * D_ * S_];
__device__ __align__(16) __half g_ctxh[(size_t)B_ * S_ * HID]; // [B,S,HID]
__device__ __align__(16) __half g_xh[(size_t)B_ * S_ * HID];
__device__ __align__(16) __half g_wh[4 * (size_t)HID * HID];

// ---------------------------------------------------------------------------
// Helpers
// ---------------------------------------------------------------------------
__device__ __forceinline__ float ex2(float x) {
    float y;
    asm("ex2.approx.f32 %0, %1;" : "=f"(y) : "f"(x));
    return y;
}
__device__ __forceinline__ uint32_t h2u(float lo, float hi) {
    uint32_t d;
    asm("cvt.rn.f16x2.f32 %0, %1, %2;" : "=r"(d) : "f"(hi), "f"(lo));
    return d;
}
// packed fp16x2 exp2 — halves MUFU pressure in the softmax
__device__ __forceinline__ uint32_t hex2(uint32_t x) {
    uint32_t y;
    asm("ex2.approx.f16x2 %0, %1;" : "=r"(y) : "r"(x));
    return y;
}

// mma.sync m16n8k16 fp16 inputs, fp32 accumulate
__device__ __forceinline__ void mma16(float* d, const uint32_t* a, const uint32_t* b) {
    asm volatile(
        "mma.sync.aligned.m16n8k16.row.col.f32.f16.f16.f32 "
        "{%0,%1,%2,%3}, {%4,%5,%6,%7}, {%8,%9}, {%0,%1,%2,%3};"
        : "+f"(d[0]), "+f"(d[1]), "+f"(d[2]), "+f"(d[3])
        : "r"(a[0]), "r"(a[1]), "r"(a[2]), "r"(a[3]), "r"(b[0]), "r"(b[1]));
}

// ldmatrix x4 (projection kernel)
__device__ __forceinline__ void ldsm4(uint32_t* r, uint32_t a) {
    asm volatile("ldmatrix.sync.aligned.m8n8.x4.shared.b16 {%0,%1,%2,%3}, [%4];"
                 : "=r"(r[0]), "=r"(r[1]), "=r"(r[2]), "=r"(r[3]) : "r"(a));
}

__device__ __forceinline__ uint32_t smem_u32(const void* p) {
    uint32_t a;
    asm("{ .reg .u64 t; cvta.to.shared.u64 t, %1; cvt.u32.u64 %0, t; }"
        : "=r"(a) : "l"(p));
    return a;
}
__device__ __forceinline__ void cpa16(uint32_t s, const void* g) {
    asm volatile("cp.async.cg.shared.global [%0], [%1], 16;" :: "r"(s), "l"(g));
}
__device__ __forceinline__ void cpa_commit() {
    asm volatile("cp.async.commit_group;" ::: "memory");
}
template <int N> __device__ __forceinline__ void cpa_wait() {
    asm volatile("cp.async.wait_group %0;" :: "n"(N) : "memory");
}

// ---------------------------------------------------------------------------
// fp32 -> fp16 conversion, single merged kernel.
// ---------------------------------------------------------------------------
__global__ void cvt_all(const float4* __restrict__ x,
                        const float4* __restrict__ wq, const float4* __restrict__ wk,
                        const float4* __restrict__ wv, const float4* __restrict__ wo)
{
    const int XN4 = B_ * S_ * HID / 4;       // 2,097,152
    const int WN4 = HID * HID / 4;           // 262,144
    int i = blockIdx.x * blockDim.x + threadIdx.x;
    if (i < XN4) {
        float4 v = x[i];
        ((uint2*)g_xh)[i] = make_uint2(h2u(v.x, v.y), h2u(v.z, v.w));
        return;
    }
    int j = i - XN4;
    if (j >= 4 * WN4) return;
    int which = j / WN4;
    int local = j - which * WN4;
    const float4* src = (which == 0) ? wq : (which == 1) ? wk : (which == 2) ? wv : wo;
    float4 v = src[local];
    ((uint2*)g_wh)[j] = make_uint2(h2u(v.x, v.y), h2u(v.z, v.w));
}

// ---------------------------------------------------------------------------
// Projection GEMM (R16 frozen): 128m x 128n block, 8 warps (64x32), BK=64,
// 3-stage / wait_group<1>, 110592 B smem, 2 CTAs/SM, row stride 36 u32.
// K/V epilogues write the fragment-pair permutation for the attention kernel.
// ---------------------------------------------------------------------------
#define PJ_A32 (128 * 36)
#define PJ_B32 (128 * 36)
static constexpr int PROJ_SMEM = 3 * (PJ_A32 + PJ_B32) * 4;  // 110592 B

__global__ __launch_bounds__(256, 2) void proj_tc(
    const __half* __restrict__ Aall, int mode,
    const float* __restrict__ bq, const float* __restrict__ bk,
    const float* __restrict__ bv, const float* __restrict__ bo,
    float* __restrict__ outflat)
{
    extern __shared__ uint32_t smu[];

    const int tid = threadIdx.x;
    const int m0  = blockIdx.y * 128;

    int which, n0g;
    const float* bias;
    if (mode == 0) {
        which = blockIdx.x >> 3;             // 0=Q 1=K 2=V (8 n-tiles each)
        n0g   = (blockIdx.x & 7) * 128;
        bias  = (which == 0) ? bq : (which == 1) ? bk : bv;
    } else {
        which = 3;
        n0g   = blockIdx.x * 128;
        bias  = bo;
    }
    const __half* Wb = g_wh + (size_t)which * HID * HID + (size_t)n0g * HID;
    const __half* Ab = Aall + (size_t)m0 * HID;

    const uint32_t sb = smem_u32(smu);

    auto load_slab = [&](int kt) {
        const int bi = kt % 3;
        const uint32_t abase = sb + (uint32_t)(bi * PJ_A32) * 4u;
        const uint32_t bbase = sb + (uint32_t)(3 * PJ_A32 + bi * PJ_B32) * 4u;
        const int k0 = kt * 64;
#pragma unroll
        for (int it = 0; it < 4; ++it) {
            int f = tid + it * 256;              // 0..1023
            int row = f >> 3, kq = (f & 7) * 8;  // halves
            cpa16(abase + (uint32_t)(row * 36 + (f & 7) * 4) * 4u,
                  Ab + (size_t)row * HID + k0 + kq);
        }
#pragma unroll
        for (int it = 0; it < 4; ++it) {
            int f = tid + it * 256;
            int row = f >> 3, kq = (f & 7) * 8;
            cpa16(bbase + (uint32_t)(row * 36 + (f & 7) * 4) * 4u,
                  Wb + (size_t)row * HID + k0 + kq);
        }
        cpa_commit();
    };

    const int w    = tid >> 5;
    const int lane = tid & 31;
    const int r    = lane >> 2;
    const int c    = lane & 3;
    const int wm   = (w & 1) * 64;     // 2 m-groups
    const int wn   = (w >> 1) * 32;    // 4 n-groups

    const uint32_t aoff = (uint32_t)((wm + (lane & 15)) * 36 + (lane >> 4) * 4);
    const uint32_t boff = (uint32_t)((wn + ((lane >> 4) * 8) + (lane & 7)) * 36
                                     + ((lane >> 3) & 1) * 4);

    float acc[4][4][4];
#pragma unroll
    for (int i = 0; i < 4; ++i)
#pragma unroll
        for (int j = 0; j < 4; ++j)
#pragma unroll
            for (int q = 0; q < 4; ++q) acc[i][j][q] = 0.f;

    load_slab(0);
    load_slab(1);

    for (int kt = 0; kt < 16; ++kt) {
        cpa_wait<1>();          // slab kt resident; kt+1 may still be in flight
        __syncthreads();        // all warps done with buffer (kt+2)%3
        if (kt + 2 < 16) load_slab(kt + 2);
        else cpa_commit();      // keep group accounting uniform

        const uint32_t abuf = sb + (uint32_t)((kt % 3) * PJ_A32) * 4u;
        const uint32_t bbuf = sb + (uint32_t)(3 * PJ_A32 + (kt % 3) * PJ_B32) * 4u;

#pragma unroll
        for (int ks = 0; ks < 4; ++ks) {          // 4 k16 chunks per BK=64
            uint32_t af[4][4];
#pragma unroll
            for (int i = 0; i < 4; ++i)
                ldsm4(af[i], abuf + (aoff + (uint32_t)(i * 576 + ks * 8)) * 4u);
            uint32_t bg[2][4];
#pragma unroll
            for (int g = 0; g < 2; ++g)
                ldsm4(bg[g], bbuf + (boff + (uint32_t)(g * 576 + ks * 8)) * 4u);
#pragma unroll
            for (int g = 0; g < 2; ++g)
#pragma unroll
                for (int i = 0; i < 4; ++i) {
                    mma16(acc[i][2 * g],     af[i], &bg[g][0]);
                    mma16(acc[i][2 * g + 1], af[i], &bg[g][2]);
                }
        }
    }

    // Epilogue
    if (mode == 0) {
        const float SCQ = 0.125f * 1.4426950408889634f;
#pragma unroll
        for (int j = 0; j < 4; ++j) {
            const int nl = n0g + wn + j * 8 + 2 * c;
            const float b0 = bias[nl], b1 = bias[nl + 1];
            const int h  = nl >> 6;
            const int dd = nl & 63;                 // even
            // fragment-pair permutation of u32 index u within 8-u32 groups
            const int u  = dd >> 1;
            const int pw = u & 7;
            const int ndd = ((u & ~7) | ((pw < 4) ? 2 * pw : 2 * pw - 7)) * 2;
#pragma unroll
            for (int i = 0; i < 4; ++i) {
                int m = m0 + wm + i * 16 + r;
                int bi = m >> 11, s = m & 2047;     // s & 15 == r < 8
                float v0 = acc[i][j][0] + b0, v1 = acc[i][j][1] + b1;
                float v2 = acc[i][j][2] + b0, v3 = acc[i][j][3] + b1;
                if (which == 0) {
                    __half* p = g_qh + (((size_t)(bi * H_ + h) * S_ + s) * D_ + dd);
                    *(uint32_t*)p = h2u(v0 * SCQ, v1 * SCQ);
                    *(uint32_t*)(p + 8 * D_) = h2u(v2 * SCQ, v3 * SCQ);
                } else if (which == 1) {
                    __half* p = g_kh + (((size_t)(bi * H_ + h) * S_ + s) * D_ + ndd);
                    *(uint32_t*)p = h2u(v0, v1);
                    *(uint32_t*)(p + 8 * D_) = h2u(v2, v3);
                } else {
                    // V transposed [B,H,D,S], s-dim permuted.
                    const int sw = (s >> 1) & 7;    // < 4 since s&15 = r < 8
                    const int ns = (s & ~15) | (4 * sw + (s & 1));
                    __half* p = g_vt + (((size_t)(bi * H_ + h) * D_ + dd) * S_ + ns);
                    p[0]      = __float2half_rn(v0);   // (dd,   s)
                    p[S_]     = __float2half_rn(v1);   // (dd+1, s)
                    p[2]      = __float2half_rn(v2);   // (dd,   s+8) -> ns+2
                    p[S_ + 2] = __float2half_rn(v3);   // (dd+1, s+8)
                }
            }
        }
    } else {
#pragma unroll
        for (int j = 0; j < 4; ++j) {
            const int n = n0g + wn + j * 8 + 2 * c;
            const float b0 = bias[n], b1 = bias[n + 1];
#pragma unroll
            for (int i = 0; i < 4; ++i) {
                int m = m0 + wm + i * 16 + r;
                float* p = outflat + (size_t)m * HID + n;
                *(float2*)p = make_float2(acc[i][j][0] + b0, acc[i][j][1] + b1);
                *(float2*)(p + 8 * HID) =
                    make_float2(acc[i][j][2] + b0, acc[i][j][3] + b1);
            }
        }
    }
}

// ---------------------------------------------------------------------------
// Flash attention R17: 128-KEY tiles, 2 buffers, wait<0> (R6-proven safe:
// each tile's load is issued one full tile-compute ahead). Softmax still per
// 64-key chunk (two chunks back-to-back inside the tile, no barrier between).
// Halves barrier count 32 -> 16; 136 MMAs/warp between barriers.
// K stage: 128 rows x 40 u32; V stage: 64 d-rows x 72 u32 (128 halves+pad).
// smem/CTA = 2*(5120+4608)*4 = 77824 B -> 2 CTAs/SM.
// ---------------------------------------------------------------------------
#define AT_KST 40
#define AT_VST 72
#define AT_KTILE (128 * AT_KST)       // 5120 u32 per K stage
#define AT_VTILE (64 * AT_VST)        // 4608 u32 per V stage
static constexpr int ATTN_SMEM = 2 * (AT_KTILE + AT_VTILE) * 4;   // 77824 B

__global__ __launch_bounds__(256, 2) void attn_tc(const float* __restrict__ head_mask)
{
    extern __shared__ uint32_t smu[];

    const int tid = threadIdx.x;
    const int bh  = blockIdx.y;
    const int s0  = blockIdx.x * 128;

    const __half* K = g_kh + (size_t)bh * S_ * D_;
    const __half* V = g_vt + (size_t)bh * D_ * S_;

    const int w    = tid >> 5;
    const int lane = tid & 31;
    const int r    = lane >> 2;
    const int c    = lane & 3;
    const int wm   = w * 16;

    const uint32_t sb = smem_u32(smu);

    // Q fragments from gmem (fp16, pre-scaled, unpermuted).
    uint32_t qf[4][4];
    {
        const uint32_t* Qp = (const uint32_t*)(g_qh + (size_t)bh * S_ * D_);
        const uint32_t* q0 = Qp + (size_t)(s0 + wm + r) * 32;
        const uint32_t* q1 = q0 + 8 * 32;
#pragma unroll
        for (int ks = 0; ks < 4; ++ks) {
            qf[ks][0] = q0[ks * 8 + c];
            qf[ks][1] = q1[ks * 8 + c];
            qf[ks][2] = q0[ks * 8 + c + 4];
            qf[ks][3] = q1[ks * 8 + c + 4];
        }
    }

    // 128-key tile load: K 128 rows x 64 halves; V 64 rows x 128 halves.
    auto load_tile = [&](int kt) {
        const int bi = kt & 1;
        const uint32_t kd = sb + (uint32_t)(bi * AT_KTILE) * 4u;
        const uint32_t vd = sb + (uint32_t)(2 * AT_KTILE + bi * AT_VTILE) * 4u;
#pragma unroll
        for (int it = 0; it < 4; ++it) {             // K: 1024 x 16B
            int f = tid + it * 256;
            int row = f >> 3;                        // 0..127
            int ch  = f & 7;
            cpa16(kd + (uint32_t)(row * AT_KST + ch * 4) * 4u,
                  K + (size_t)(kt * 128 + row) * D_ + ch * 8);
        }
#pragma unroll
        for (int it = 0; it < 4; ++it) {             // V: 1024 x 16B
            int f = tid + it * 256;
            int row = f >> 4;                        // 0..63 (d)
            int ch  = f & 15;
            cpa16(vd + (uint32_t)(row * AT_VST + ch * 4) * 4u,
                  V + (size_t)row * S_ + kt * 128 + ch * 8);
        }
        cpa_commit();
    };

    float m0 = -1e30f, m1 = -1e30f;
    float oacc[8][4];
#pragma unroll
    for (int j = 0; j < 8; ++j)
#pragma unroll
        for (int q = 0; q < 4; ++q) oacc[j][q] = 0.f;
    float lacc[4] = {0.f, 0.f, 0.f, 0.f};

    load_tile(0);

    const uint32_t onesb[2] = {0x3C003C00u, 0x3C003C00u};   // fp16 1.0 x4

    for (int kt = 0; kt < S_ / 128; ++kt) {
        cpa_wait<0>();          // tile kt resident (issued one tile-compute ago)
        __syncthreads();        // all warps done with buffer (kt+1)&1
        if (kt + 1 < S_ / 128) load_tile(kt + 1);

        const uint32_t* kb = smu + (size_t)(kt & 1) * AT_KTILE;
        const uint32_t* vb = smu + 2 * AT_KTILE + (size_t)(kt & 1) * AT_VTILE;

        // two 64-key chunks, no barrier between (both resident)
#pragma unroll
        for (int chnk = 0; chnk < 2; ++chnk) {
            const uint32_t* ks_ = kb + chnk * 64 * AT_KST;
            const uint32_t* vs_ = vb + chnk * 32;       // u32 col offset

            // --- S = Q @ K^T (log2e space) ---
            float sacc[8][4];
#pragma unroll
            for (int j = 0; j < 8; ++j)
#pragma unroll
                for (int q = 0; q < 4; ++q) sacc[j][q] = 0.f;

#pragma unroll
            for (int ksb = 0; ksb < 4; ++ksb) {
#pragma unroll
                for (int j = 0; j < 8; ++j) {
                    uint2 b2 = *(const uint2*)(ks_ + (8 * j + r) * AT_KST + 8 * ksb + 2 * c);
                    uint32_t bf[2] = { b2.x, b2.y };
                    mma16(sacc[j], qf[ksb], bf);
                }
            }

            // --- register softmax max (rows r, r+8) ---
            float mx0 = sacc[0][0], mx1 = sacc[0][2];
#pragma unroll
            for (int j = 0; j < 8; ++j) {
                mx0 = fmaxf(mx0, fmaxf(sacc[j][0], sacc[j][1]));
                mx1 = fmaxf(mx1, fmaxf(sacc[j][2], sacc[j][3]));
            }
            mx0 = fmaxf(mx0, __shfl_xor_sync(0xffffffffu, mx0, 1));
            mx0 = fmaxf(mx0, __shfl_xor_sync(0xffffffffu, mx0, 2));
            mx1 = fmaxf(mx1, __shfl_xor_sync(0xffffffffu, mx1, 1));
            mx1 = fmaxf(mx1, __shfl_xor_sync(0xffffffffu, mx1, 2));

            const float nm0 = fmaxf(m0, mx0);
            const float nm1 = fmaxf(m1, mx1);
            const float f0 = ex2(m0 - nm0);
            const float f1 = ex2(m1 - nm1);
            m0 = nm0; m1 = nm1;

            // exp via packed fp16x2 ex2
            uint32_t pf[4][4];
#pragma unroll
            for (int t = 0; t < 4; ++t) {
                pf[t][0] = hex2(h2u(sacc[2 * t][0] - nm0,     sacc[2 * t][1] - nm0));
                pf[t][1] = hex2(h2u(sacc[2 * t][2] - nm1,     sacc[2 * t][3] - nm1));
                pf[t][2] = hex2(h2u(sacc[2 * t + 1][0] - nm0, sacc[2 * t + 1][1] - nm0));
                pf[t][3] = hex2(h2u(sacc[2 * t + 1][2] - nm1, sacc[2 * t + 1][3] - nm1));
            }

            // --- rescale accumulators (unconditional, overlaps with MMAs) ---
#pragma unroll
            for (int j = 0; j < 8; ++j) {
                oacc[j][0] *= f0; oacc[j][1] *= f0;
                oacc[j][2] *= f1; oacc[j][3] *= f1;
            }
            lacc[0] *= f0; lacc[2] *= f1;

            // --- O += P@V and l += P@1 ---
#pragma unroll
            for (int t = 0; t < 4; ++t) {
                mma16(lacc, pf[t], onesb);
#pragma unroll
                for (int j = 0; j < 8; ++j) {
                    uint2 b2 = *(const uint2*)(vs_ + (8 * j + r) * AT_VST + 8 * t + 2 * c);
                    uint32_t bf[2] = { b2.x, b2.y };
                    mma16(oacc[j], pf[t], bf);
                }
            }
        }
    }

    // Epilogue: normalize, head-mask, write ctx fp16 [B,S,HID]
    const int bix = bh >> 4;
    const int h   = bh & 15;
    const float mask = head_mask[h];
    const float inv0 = mask / lacc[0];
    const float inv1 = mask / lacc[2];
    const int s = s0 + wm + r;
#pragma unroll
    for (int j = 0; j < 8; ++j) {
        int dd = 8 * j + 2 * c;
        __half* p = g_ctxh + ((size_t)bix * S_ + s) * HID + h * 64 + dd;
        *(uint32_t*)p = h2u(oacc[j][0] * inv0, oacc[j][1] * inv0);
        *(uint32_t*)(p + 8 * HID) = h2u(oacc[j][2] * inv1, oacc[j][3] * inv1);
    }
}

// ---------------------------------------------------------------------------
extern "C" void kernel_launch(void* const* d_in, const int* in_sizes, int n_in,
                              void* d_out, int out_size)
{
    const float* x  = (const float*)d_in[0];
    const float* Wq = (const float*)d_in[1];
    const float* bq = (const float*)d_in[2];
    const float* Wk = (const float*)d_in[3];
    const float* bk = (const float*)d_in[4];
    const float* Wv = (const float*)d_in[5];
    const float* bv = (const float*)d_in[6];
    const float* Wo = (const float*)d_in[7];
    const float* bo = (const float*)d_in[8];
    const float* head_mask = (const float*)d_in[9];
    float* out = (float*)d_out;

    static bool attr_set = false;
    if (!attr_set) {
        cudaFuncSetAttribute(proj_tc, cudaFuncAttributeMaxDynamicSharedMemorySize, PROJ_SMEM);
        cudaFuncSetAttribute(attn_tc, cudaFuncAttributeMaxDynamicSharedMemorySize, ATTN_SMEM);
        attr_set = true;
    }

    // fp32 -> fp16 conversion (x + all four weight matrices, one launch)
    const int total4 = B_ * S_ * HID / 4 + 4 * (HID * HID / 4);   // 3,145,728
    cvt_all<<<(total4 + 255) / 256, 256>>>((const float4*)x,
                                           (const float4*)Wq, (const float4*)Wk,
                                           (const float4*)Wv, (const float4*)Wo);

    __half* xh_dev;  cudaGetSymbolAddress((void**)&xh_dev,  g_xh);
    __half* ctx_dev; cudaGetSymbolAddress((void**)&ctx_dev, g_ctxh);

    // QKV projection: 24 x 64 blocks of 128m x 128n (8 n-tiles per matrix)
    proj_tc<<<dim3(24, 64), 256, PROJ_SMEM>>>(xh_dev, 0, bq, bk, bv, bo, nullptr);

    // Attention: 16 q-tiles x 64 bh
    attn_tc<<<dim3(16, 64), 256, ATTN_SMEM>>>(head_mask);

    // O projection: 8 x 64 blocks of 128m x 128n
    proj_tc<<<dim3(8, 64), 256, PROJ_SMEM>>>(ctx_dev, 1, bq, bk, bv, bo, out);
}